// round 14
// baseline (speedup 1.0000x reference)
#include <cuda_runtime.h>
#include <cuda_fp16.h>
#include <stdint.h>

#define L_SEQ   2048
#define BATCH   16
#define N_IN    1024
#define N_OUT   1024
#define M_ROWS  (L_SEQ * BATCH)      // 32768
#define N_COLS  (2 * N_OUT)          // 2048
#define K_DIM   1024
#define NCH     (BATCH * N_OUT)      // 16384 chains

#define CS_OFF      0
#define CFINAL_OFF  (M_ROWS * N_OUT)
#define FORGET_OFF  (M_ROWS * N_OUT + BATCH * N_OUT)

// fp16 operands. A: [32768,1024] k-contig. B = fp16(W^T): [2048,1024].
__device__ __half g_Ah[(size_t)M_ROWS * K_DIM];
__device__ __half g_Bh[(size_t)N_COLS * K_DIM];

// scan scratch. One segment = one GEMM M-tile = 8 l-steps.
#define SEGS 256
#define SEG_LEN (L_SEQ / SEGS)       // 8
__device__ float g_F  [SEGS][NCH];
__device__ float g_U  [SEGS][NCH];
__device__ float g_Cin[SEGS][NCH];

// ---------------------------------------------------------------------------
__device__ __forceinline__ uint32_t s2u(const void* p) {
    uint32_t r;
    asm("{ .reg .u64 t; cvta.to.shared.u64 t, %1; cvt.u32.u64 %0, t; }"
        : "=r"(r) : "l"(p));
    return r;
}
__device__ __forceinline__ void cp16(uint32_t saddr, const void* gptr) {
    uint64_t g = (uint64_t)__cvta_generic_to_global(gptr);
    asm volatile("cp.async.cg.shared.global [%0], [%1], 16;"
                 :: "r"(saddr), "l"(g) : "memory");
}
__device__ __forceinline__ void cp_commit() {
    asm volatile("cp.async.commit_group;" ::: "memory");
}
template <int N>
__device__ __forceinline__ void cp_wait() {
    asm volatile("cp.async.wait_group %0;" :: "n"(N) : "memory");
}
__device__ __forceinline__ void ldsm4(uint32_t* r, uint32_t addr) {
    asm volatile("ldmatrix.sync.aligned.m8n8.x4.shared.b16 {%0,%1,%2,%3}, [%4];"
                 : "=r"(r[0]), "=r"(r[1]), "=r"(r[2]), "=r"(r[3]) : "r"(addr));
}
__device__ __forceinline__ void mma16816(float* d, const uint32_t* a, const uint32_t* b) {
    asm volatile(
        "mma.sync.aligned.m16n8k16.row.col.f32.f16.f16.f32 "
        "{%0,%1,%2,%3}, {%4,%5,%6,%7}, {%8,%9}, {%0,%1,%2,%3};"
        : "+f"(d[0]), "+f"(d[1]), "+f"(d[2]), "+f"(d[3])
        : "r"(a[0]), "r"(a[1]), "r"(a[2]), "r"(a[3]), "r"(b[0]), "r"(b[1]));
}
__device__ __forceinline__ uint32_t swz(uint32_t off) {
    return off ^ ((off >> 3) & 0x70);
}

// ---------------------------------------------------------------------------
// Operand prep
// ---------------------------------------------------------------------------
__global__ __launch_bounds__(256)
void convert_a_kernel(const float* __restrict__ A) {
    size_t i = ((size_t)blockIdx.x * 256 + threadIdx.x) * 8;
    float4 v0 = *reinterpret_cast<const float4*>(A + i);
    float4 v1 = *reinterpret_cast<const float4*>(A + i + 4);
    __half2 h0 = __floats2half2_rn(v0.x, v0.y);
    __half2 h1 = __floats2half2_rn(v0.z, v0.w);
    __half2 h2 = __floats2half2_rn(v1.x, v1.y);
    __half2 h3 = __floats2half2_rn(v1.z, v1.w);
    uint4 pk;
    pk.x = *reinterpret_cast<uint32_t*>(&h0);
    pk.y = *reinterpret_cast<uint32_t*>(&h1);
    pk.z = *reinterpret_cast<uint32_t*>(&h2);
    pk.w = *reinterpret_cast<uint32_t*>(&h3);
    *reinterpret_cast<uint4*>(g_Ah + i) = pk;
}

__global__ __launch_bounds__(256)
void convert_b_kernel(const float* __restrict__ W) {
    __shared__ float t[32][33];
    int n0 = blockIdx.x * 32;
    int k0 = blockIdx.y * 32;
    int tx = threadIdx.x & 31;
    int ty = threadIdx.x >> 5;
#pragma unroll
    for (int i = 0; i < 4; i++)
        t[ty + i * 8][tx] = W[(size_t)(k0 + ty + i * 8) * N_COLS + n0 + tx];
    __syncthreads();
#pragma unroll
    for (int i = 0; i < 4; i++) {
        int n = ty + i * 8;
        g_Bh[(size_t)(n0 + n) * K_DIM + k0 + tx] = __float2half_rn(t[tx][n]);
    }
}

// ---------------------------------------------------------------------------
// GEMM: BM=128, BN=128, BK=64, 256 threads = 8 warps (2M x 4N),
// warp tile 64x32. 3-stage cp.async pipeline, 2 CTAs per SM.
// Fragment double-buffering: ldsm(ks+1) issued before mma(ks).
// Epilogue: gates + per-segment scan summaries (fused phaseA, SEG_LEN=8).
// ---------------------------------------------------------------------------
#define BK 64
#define OFF_A 0
#define OFF_B 16384
#define STAGE_BYTES 32768
#define NSTAGE 3
#define SMEM_TOTAL (NSTAGE * STAGE_BYTES)   // 98304
#define NCHUNK (K_DIM / BK)                 // 16

__device__ __forceinline__ void load_stage(uint32_t sbase, int tid,
                                           int rowBase, int colBase, int k0) {
    const char* ah = reinterpret_cast<const char*>(g_Ah);
    const char* bh = reinterpret_cast<const char*>(g_Bh);
#pragma unroll
    for (int i = 0; i < 4; i++) {               // A: 128 rows x 8 x 16B
        int idx = i * 256 + tid;
        int row = idx >> 3, c = idx & 7;
        uint32_t so = swz((uint32_t)(row * 128 + c * 16));
        size_t go = ((size_t)(rowBase + row) * K_DIM + k0) * 2 + c * 16;
        cp16(sbase + OFF_A + so, ah + go);
    }
#pragma unroll
    for (int i = 0; i < 4; i++) {               // B: 128 rows x 8 x 16B
        int idx = i * 256 + tid;
        int row = idx >> 3, c = idx & 7;
        uint32_t so = swz((uint32_t)(row * 128 + c * 16));
        size_t go = ((size_t)(colBase + row) * K_DIM + k0) * 2 + c * 16;
        cp16(sbase + OFF_B + so, bh + go);
    }
    cp_commit();
}

__global__ __launch_bounds__(256, 2)
void gemm_mma_kernel(const float* __restrict__ bias,
                     float* __restrict__ u0_out,
                     float* __restrict__ f_out) {
    extern __shared__ __align__(128) char smem[];
    const uint32_t sb = s2u(smem);
    const int tid = threadIdx.x;
    const int lid = tid & 31;
    const int wid = tid >> 5;            // 0..7
    const int warpM = wid & 1;           // 2 x 64-row slices
    const int warpN = wid >> 1;          // 4 x 32-col slices
    const int colBase = blockIdx.x * 128;
    const int rowBase = blockIdx.y * 128;

    float acc[4][4][4];
#pragma unroll
    for (int mi = 0; mi < 4; mi++)
#pragma unroll
        for (int ni = 0; ni < 4; ni++)
#pragma unroll
            for (int e = 0; e < 4; e++)
                acc[mi][ni][e] = 0.0f;

    // prologue: fill 3 stages (chunks 0..2)
#pragma unroll
    for (int s = 0; s < NSTAGE; s++)
        load_stage(sb + s * STAGE_BYTES, tid, rowBase, colBase, s * BK);

    // Precomputed ldsm bases (kIn2 folded into swizzle).
    const int aRowIn = warpM * 64 + (lid & 15);
    const int aKIn2  = ((lid >> 4) * 8) * 2;          // 0 or 16 (bit 4)
    const int bRowIn = warpN * 32 + (lid & 7) + ((lid >> 4) & 1) * 8;
    const int bKIn2  = (((lid >> 3) & 1) * 8) * 2;    // 0 or 16 (bit 4)
    uint32_t aBase[4], bBase[2];
#pragma unroll
    for (int mi = 0; mi < 4; mi++)
        aBase[mi] = swz((uint32_t)((aRowIn + mi * 16) * 128 + aKIn2)) + OFF_A;
#pragma unroll
    for (int nt = 0; nt < 2; nt++)
        bBase[nt] = swz((uint32_t)((bRowIn + nt * 16) * 128 + bKIn2)) + OFF_B;

    for (int c = 0; c < NCHUNK; c++) {
        if (c == 0)       cp_wait<2>();
        else if (c < 15)  cp_wait<1>();
        else              cp_wait<0>();
        __syncthreads();   // data visible + buffer (c-1)%3 drained by all warps

        // issue chunk c+2 into buffer (c+2)%3 == (c-1)%3 (free after barrier)
        if (c >= 1 && c + 2 < NCHUNK)
            load_stage(sb + ((c + 2) % 3) * STAGE_BYTES, tid,
                       rowBase, colBase, (c + 2) * BK);

        const uint32_t sbase = sb + (c % 3) * STAGE_BYTES;
        uint32_t aP[4], bP[2];
#pragma unroll
        for (int mi = 0; mi < 4; mi++) aP[mi] = sbase + aBase[mi];
#pragma unroll
        for (int nt = 0; nt < 2; nt++) bP[nt] = sbase + bBase[nt];

        // fragment double-buffer: preload ks=0, then ldsm(ks+1) before mma(ks)
        uint32_t ah[2][4][4], bf[2][2][4];
#pragma unroll
        for (int mi = 0; mi < 4; mi++) ldsm4(ah[0][mi], aP[mi]);
#pragma unroll
        for (int nt = 0; nt < 2; nt++) ldsm4(bf[0][nt], bP[nt]);

#pragma unroll
        for (int ks = 0; ks < 4; ks++) {
            const int cur = ks & 1;
            const int nxt = cur ^ 1;
            if (ks < 3) {
                const uint32_t kx = (uint32_t)((ks + 1) * 32);
#pragma unroll
                for (int mi = 0; mi < 4; mi++) ldsm4(ah[nxt][mi], aP[mi] ^ kx);
#pragma unroll
                for (int nt = 0; nt < 2; nt++) ldsm4(bf[nxt][nt], bP[nt] ^ kx);
            }
#pragma unroll
            for (int mi = 0; mi < 4; mi++)
#pragma unroll
                for (int ni = 0; ni < 4; ni++)
                    mma16816(acc[mi][ni], ah[cur][mi],
                             &bf[cur][ni >> 1][(ni & 1) * 2]);
        }
    }
    __syncthreads();   // safe to reuse smem for scan partials

    // ------------- epilogue: gates + stores + fused segment summary -------------
    float2* part = reinterpret_cast<float2*>(smem);   // [wM(2)][wN(4)][ni(4)][half(2)][lane(32)]

    const int rBase = rowBase + warpM * 64 + (lid >> 2);
    const int oLane = (lid & 3);

#pragma unroll
    for (int ni = 0; ni < 4; ni++) {
        const int o = ((colBase + warpN * 32 + ni * 8) >> 1) + oLane;
        const float fb = __ldg(bias + N_OUT + o);
        float F0 = 1.0f, U0 = 0.0f, F1 = 1.0f, U1 = 0.0f;
#pragma unroll
        for (int mi = 0; mi < 4; mi++) {
            const int r0 = rBase + mi * 16;
            const int r1 = r0 + 8;
            float f0 = 1.0f / (1.0f + __expf(-(acc[mi][ni][1] + fb)));
            float u0 = acc[mi][ni][0] * (1.0f - f0);
            float f1 = 1.0f / (1.0f + __expf(-(acc[mi][ni][3] + fb)));
            float u1 = acc[mi][ni][2] * (1.0f - f1);
            u0_out[(size_t)r0 * N_OUT + o] = u0;
            f_out [(size_t)r0 * N_OUT + o] = f0;
            u0_out[(size_t)r1 * N_OUT + o] = u1;
            f_out [(size_t)r1 * N_OUT + o] = f1;
            U0 = fmaf(U0, f0, u0); F0 *= f0;
            U1 = fmaf(U1, f1, u1); F1 *= f1;
        }
        int base = ((warpM * 4 + warpN) * 4 + ni) * 64;
        part[base + lid]      = make_float2(F0, U0);
        part[base + 32 + lid] = make_float2(F1, U1);
    }
    __syncthreads();

    // combine partials across warpM (l-order) and write g_F/g_U
    const int seg = blockIdx.y;
#pragma unroll
    for (int it = 0; it < 4; it++) {
        int item = tid + it * 256;              // [wN(2b)|ni(2b)|half(1b)|lane(5b)]
        int iwN   = item >> 8;
        int ini   = (item >> 6) & 3;
        int ihalf = (item >> 5) & 1;
        int ilane = item & 31;
        float F = 1.0f, U = 0.0f;
#pragma unroll
        for (int w = 0; w < 2; w++) {
            float2 p = part[(((w * 4 + iwN) * 4 + ini) * 2 + ihalf) * 32 + ilane];
            U = fmaf(U, p.x, p.y);
            F *= p.x;
        }
        int b = (ilane >> 2) + ihalf * 8;
        int j = b * N_OUT + blockIdx.x * 64 + iwN * 16 + ini * 4 + (ilane & 3);
        g_F[seg][j] = F;
        g_U[seg][j] = U;
    }
}

// ---------------------------------------------------------------------------
// Phase B: warp-parallel affine scan over 256 segments.
// One warp per chain (lane owns 8 segments); 4 chains per 128-thread block.
// Cin written in place over sF (own-warp row only).
// ---------------------------------------------------------------------------
__global__ __launch_bounds__(128)
void scan_phaseB(const float* __restrict__ c_init,
                 float* __restrict__ c_final) {
    __shared__ float sF[4][SEGS];
    __shared__ float sU[4][SEGS];

    const int tid = threadIdx.x;
    const int jBase = blockIdx.x * 4;

#pragma unroll
    for (int it = 0; it < 8; it++) {
        int idx = it * 128 + tid;          // 0..1023
        int s = idx >> 2, jj = idx & 3;
        sF[jj][s] = g_F[s][jBase + jj];
        sU[jj][s] = g_U[s][jBase + jj];
    }
    __syncthreads();

    const int w = tid >> 5;        // 0..3
    const int lane = tid & 31;
    const int j = jBase + w;

    float Pf[8], Pu[8];
#pragma unroll
    for (int k = 0; k < 8; k++) {
        float Fk = sF[w][lane * 8 + k];
        float Uk = sU[w][lane * 8 + k];
        if (k == 0) { Pf[0] = Fk; Pu[0] = Uk; }
        else        { Pf[k] = Pf[k - 1] * Fk; Pu[k] = fmaf(Pu[k - 1], Fk, Uk); }
    }

    float tf = Pf[7], tu = Pu[7];
#pragma unroll
    for (int d = 1; d < 32; d <<= 1) {
        float of = __shfl_up_sync(0xffffffffu, tf, d);
        float ou = __shfl_up_sync(0xffffffffu, tu, d);
        if (lane >= d) {
            tu = fmaf(ou, tf, tu);
            tf = of * tf;
        }
    }
    float ef = __shfl_up_sync(0xffffffffu, tf, 1);
    float eu = __shfl_up_sync(0xffffffffu, tu, 1);
    if (lane == 0) { ef = 1.0f; eu = 0.0f; }

    const float c0 = c_init[j];
    sF[w][lane * 8] = fmaf(c0, ef, eu);
#pragma unroll
    for (int k = 1; k < 8; k++)
        sF[w][lane * 8 + k] = fmaf(c0, ef * Pf[k - 1], fmaf(eu, Pf[k - 1], Pu[k - 1]));

    if (lane == 31)
        c_final[j] = fmaf(c0, tf, tu);

    __syncthreads();
#pragma unroll
    for (int it = 0; it < 8; it++) {
        int idx = it * 128 + tid;
        int s = idx >> 2, jj = idx & 3;
        g_Cin[s][jBase + jj] = sF[jj][s];
    }
}

// ---------------------------------------------------------------------------
// Phase C: replay. 256 segments x 8 steps.
// ---------------------------------------------------------------------------
__global__ __launch_bounds__(256)
void scan_phaseC(float* __restrict__ cs,
                 const float* __restrict__ f) {
    const int j = blockIdx.x * 256 + threadIdx.x;
    const int s = blockIdx.y;
    size_t idx = (size_t)s * SEG_LEN * NCH + j;
    float c = g_Cin[s][j];
#pragma unroll
    for (int t = 0; t < SEG_LEN; t++) {
        float ft = f[idx];
        float ut = cs[idx];
        c = fmaf(c, ft, ut);
        cs[idx] = c;
        idx += NCH;
    }
}

// ---------------------------------------------------------------------------
extern "C" void kernel_launch(void* const* d_in, const int* in_sizes, int n_in,
                              void* d_out, int out_size)
{
    const float* input  = (const float*)d_in[0];
    const float* c_init = (const float*)d_in[1];
    const float* weight = (const float*)d_in[2];
    const float* bias   = (const float*)d_in[3];

    float* out    = (float*)d_out;
    float* cs     = out + CS_OFF;
    float* cfin   = out + CFINAL_OFF;
    float* forget = out + FORGET_OFF;

    cudaFuncSetAttribute(gemm_mma_kernel,
                         cudaFuncAttributeMaxDynamicSharedMemorySize, SMEM_TOTAL);

    convert_a_kernel<<<(M_ROWS * K_DIM) / (256 * 8), 256>>>(input);
    convert_b_kernel<<<dim3(N_COLS / 32, K_DIM / 32), 256>>>(weight);

    dim3 grid(N_COLS / 128, M_ROWS / 128);   // (16, 256) — blockIdx.y = segment
    gemm_mma_kernel<<<grid, 256, SMEM_TOTAL>>>(bias, cs, forget);

    scan_phaseB<<<NCH / 4, 128>>>(c_init, cfin);   // 4096 blocks, 4 chains each
    dim3 cgrid(NCH / 256, SEGS);
    scan_phaseC<<<cgrid, 256>>>(cs, forget);
}

// round 15
// speedup vs baseline: 1.0540x; 1.0540x over previous
#include <cuda_runtime.h>
#include <cuda_fp16.h>
#include <stdint.h>

#define L_SEQ   2048
#define BATCH   16
#define N_IN    1024
#define N_OUT   1024
#define M_ROWS  (L_SEQ * BATCH)      // 32768
#define N_COLS  (2 * N_OUT)          // 2048
#define K_DIM   1024
#define NCH     (BATCH * N_OUT)      // 16384 chains

#define CS_OFF      0
#define CFINAL_OFF  (M_ROWS * N_OUT)
#define FORGET_OFF  (M_ROWS * N_OUT + BATCH * N_OUT)

// fp16 operands. A: [32768,1024] k-contig. B = fp16(W^T): [2048,1024],
// rows gate-permuted within each 32-row slice (4x4 transpose of gate index).
__device__ __half g_Ah[(size_t)M_ROWS * K_DIM];
__device__ __half g_Bh[(size_t)N_COLS * K_DIM];

// scan scratch. One segment = one GEMM M-tile = 8 l-steps.
#define SEGS 256
#define SEG_LEN (L_SEQ / SEGS)       // 8
__device__ float g_F  [SEGS][NCH];
__device__ float g_U  [SEGS][NCH];
__device__ float g_Cin[SEGS][NCH];

// ---------------------------------------------------------------------------
__device__ __forceinline__ uint32_t s2u(const void* p) {
    uint32_t r;
    asm("{ .reg .u64 t; cvta.to.shared.u64 t, %1; cvt.u32.u64 %0, t; }"
        : "=r"(r) : "l"(p));
    return r;
}
__device__ __forceinline__ void cp16(uint32_t saddr, const void* gptr) {
    uint64_t g = (uint64_t)__cvta_generic_to_global(gptr);
    asm volatile("cp.async.cg.shared.global [%0], [%1], 16;"
                 :: "r"(saddr), "l"(g) : "memory");
}
__device__ __forceinline__ void cp_commit() {
    asm volatile("cp.async.commit_group;" ::: "memory");
}
template <int N>
__device__ __forceinline__ void cp_wait() {
    asm volatile("cp.async.wait_group %0;" :: "n"(N) : "memory");
}
__device__ __forceinline__ void ldsm4(uint32_t* r, uint32_t addr) {
    asm volatile("ldmatrix.sync.aligned.m8n8.x4.shared.b16 {%0,%1,%2,%3}, [%4];"
                 : "=r"(r[0]), "=r"(r[1]), "=r"(r[2]), "=r"(r[3]) : "r"(addr));
}
__device__ __forceinline__ void mma16816(float* d, const uint32_t* a, const uint32_t* b) {
    asm volatile(
        "mma.sync.aligned.m16n8k16.row.col.f32.f16.f16.f32 "
        "{%0,%1,%2,%3}, {%4,%5,%6,%7}, {%8,%9}, {%0,%1,%2,%3};"
        : "+f"(d[0]), "+f"(d[1]), "+f"(d[2]), "+f"(d[3])
        : "r"(a[0]), "r"(a[1]), "r"(a[2]), "r"(a[3]), "r"(b[0]), "r"(b[1]));
}
__device__ __forceinline__ uint32_t swz(uint32_t off) {
    return off ^ ((off >> 3) & 0x70);
}
__device__ __forceinline__ float sigmoidf_(float x) {
    return 1.0f / (1.0f + __expf(-x));
}

// ---------------------------------------------------------------------------
// Operand prep
// ---------------------------------------------------------------------------
__global__ __launch_bounds__(256)
void convert_a_kernel(const float* __restrict__ A) {
    size_t i = ((size_t)blockIdx.x * 256 + threadIdx.x) * 8;
    float4 v0 = *reinterpret_cast<const float4*>(A + i);
    float4 v1 = *reinterpret_cast<const float4*>(A + i + 4);
    __half2 h0 = __floats2half2_rn(v0.x, v0.y);
    __half2 h1 = __floats2half2_rn(v0.z, v0.w);
    __half2 h2 = __floats2half2_rn(v1.x, v1.y);
    __half2 h3 = __floats2half2_rn(v1.z, v1.w);
    uint4 pk;
    pk.x = *reinterpret_cast<uint32_t*>(&h0);
    pk.y = *reinterpret_cast<uint32_t*>(&h1);
    pk.z = *reinterpret_cast<uint32_t*>(&h2);
    pk.w = *reinterpret_cast<uint32_t*>(&h3);
    *reinterpret_cast<uint4*>(g_Ah + i) = pk;
}

// Transpose W[k][n] -> B[n_phys][k] with gate permutation: within each
// 32-row (16-gate) slice, physical gate gp = (g&3)*4 + (g>>2).
__global__ __launch_bounds__(256)
void convert_b_kernel(const float* __restrict__ W) {
    __shared__ float t[32][33];
    int n0 = blockIdx.x * 32;
    int k0 = blockIdx.y * 32;
    int tx = threadIdx.x & 31;
    int ty = threadIdx.x >> 5;
#pragma unroll
    for (int i = 0; i < 4; i++)
        t[ty + i * 8][tx] = W[(size_t)(k0 + ty + i * 8) * N_COLS + n0 + tx];
    __syncthreads();
#pragma unroll
    for (int i = 0; i < 4; i++) {
        int n = ty + i * 8;                 // 0..31 within slice
        int g   = n >> 1, par = n & 1;      // gate within slice, parity
        int gp  = ((g & 3) << 2) | (g >> 2);
        int n_phys = n0 + (gp << 1) + par;
        g_Bh[(size_t)n_phys * K_DIM + k0 + tx] = __float2half_rn(t[tx][n]);
    }
}

// ---------------------------------------------------------------------------
// GEMM: BM=128, BN=128, BK=64, 256 threads = 8 warps (2M x 4N),
// warp tile 64x32. 3-stage cp.async pipeline, 2 CTAs per SM.
// Gate-permuted B: lane c owns logical gates oBase+4c+{0..3} across ni tiles
// -> float4 output stores. Fused phaseA summaries, SEG_LEN=8.
// ---------------------------------------------------------------------------
#define BK 64
#define OFF_A 0
#define OFF_B 16384
#define STAGE_BYTES 32768
#define NSTAGE 3
#define SMEM_TOTAL (NSTAGE * STAGE_BYTES)   // 98304
#define NCHUNK (K_DIM / BK)                 // 16

__device__ __forceinline__ void load_stage(uint32_t sbase, int tid,
                                           int rowBase, int colBase, int k0) {
    const char* ah = reinterpret_cast<const char*>(g_Ah);
    const char* bh = reinterpret_cast<const char*>(g_Bh);
#pragma unroll
    for (int i = 0; i < 4; i++) {               // A: 128 rows x 8 x 16B
        int idx = i * 256 + tid;
        int row = idx >> 3, c = idx & 7;
        uint32_t so = swz((uint32_t)(row * 128 + c * 16));
        size_t go = ((size_t)(rowBase + row) * K_DIM + k0) * 2 + c * 16;
        cp16(sbase + OFF_A + so, ah + go);
    }
#pragma unroll
    for (int i = 0; i < 4; i++) {               // B: 128 rows x 8 x 16B
        int idx = i * 256 + tid;
        int row = idx >> 3, c = idx & 7;
        uint32_t so = swz((uint32_t)(row * 128 + c * 16));
        size_t go = ((size_t)(colBase + row) * K_DIM + k0) * 2 + c * 16;
        cp16(sbase + OFF_B + so, bh + go);
    }
    cp_commit();
}

__global__ __launch_bounds__(256, 2)
void gemm_mma_kernel(const float* __restrict__ bias,
                     float* __restrict__ u0_out,
                     float* __restrict__ f_out) {
    extern __shared__ __align__(128) char smem[];
    const uint32_t sb = s2u(smem);
    const int tid = threadIdx.x;
    const int lid = tid & 31;
    const int wid = tid >> 5;            // 0..7
    const int warpM = wid & 1;           // 2 x 64-row slices
    const int warpN = wid >> 1;          // 4 x 32-col slices
    const int colBase = blockIdx.x * 128;
    const int rowBase = blockIdx.y * 128;

    float acc[4][4][4];
#pragma unroll
    for (int mi = 0; mi < 4; mi++)
#pragma unroll
        for (int ni = 0; ni < 4; ni++)
#pragma unroll
            for (int e = 0; e < 4; e++)
                acc[mi][ni][e] = 0.0f;

    // prologue: fill 3 stages (chunks 0..2)
#pragma unroll
    for (int s = 0; s < NSTAGE; s++)
        load_stage(sb + s * STAGE_BYTES, tid, rowBase, colBase, s * BK);

    // Precomputed ldsm bases (kIn2 folded into swizzle).
    const int aRowIn = warpM * 64 + (lid & 15);
    const int aKIn2  = ((lid >> 4) * 8) * 2;
    const int bRowIn = warpN * 32 + (lid & 7) + ((lid >> 4) & 1) * 8;
    const int bKIn2  = (((lid >> 3) & 1) * 8) * 2;
    uint32_t aBase[4], bBase[2];
#pragma unroll
    for (int mi = 0; mi < 4; mi++)
        aBase[mi] = swz((uint32_t)((aRowIn + mi * 16) * 128 + aKIn2)) + OFF_A;
#pragma unroll
    for (int nt = 0; nt < 2; nt++)
        bBase[nt] = swz((uint32_t)((bRowIn + nt * 16) * 128 + bKIn2)) + OFF_B;

    for (int c = 0; c < NCHUNK; c++) {
        if (c == 0)       cp_wait<2>();
        else if (c < 15)  cp_wait<1>();
        else              cp_wait<0>();
        __syncthreads();

        if (c >= 1 && c + 2 < NCHUNK)
            load_stage(sb + ((c + 2) % 3) * STAGE_BYTES, tid,
                       rowBase, colBase, (c + 2) * BK);

        const uint32_t sbase = sb + (c % 3) * STAGE_BYTES;
        uint32_t aP[4], bP[2];
#pragma unroll
        for (int mi = 0; mi < 4; mi++) aP[mi] = sbase + aBase[mi];
#pragma unroll
        for (int nt = 0; nt < 2; nt++) bP[nt] = sbase + bBase[nt];

#pragma unroll
        for (int ks = 0; ks < 4; ks++) {
            const uint32_t kx = (uint32_t)(ks * 32);
            uint32_t ah[4][4];
#pragma unroll
            for (int mi = 0; mi < 4; mi++)
                ldsm4(ah[mi], aP[mi] ^ kx);
            uint32_t bh[4][2];
#pragma unroll
            for (int nt = 0; nt < 2; nt++) {
                uint32_t r[4];
                ldsm4(r, bP[nt] ^ kx);
                bh[nt * 2][0] = r[0]; bh[nt * 2][1] = r[1];
                bh[nt * 2 + 1][0] = r[2]; bh[nt * 2 + 1][1] = r[3];
            }
#pragma unroll
            for (int mi = 0; mi < 4; mi++)
#pragma unroll
                for (int ni = 0; ni < 4; ni++)
                    mma16816(acc[mi][ni], ah[mi], bh[ni]);
        }
    }
    __syncthreads();   // safe to reuse smem for scan partials

    // ------------- epilogue: gates (float4 stores) + fused summary -------------
    // Gate permutation: physical tile ni, lane c holds LOGICAL gate
    // oBase + 4c + ni, so the 4 ni values per lane are 4 consecutive gates.
    float2* part = reinterpret_cast<float2*>(smem);   // [wM][wN][half][lane][ni]

    const int rBase = rowBase + warpM * 64 + (lid >> 2);
    const int oBase = ((colBase + warpN * 32) >> 1) + (lid & 3) * 4;

    float fb[4];
#pragma unroll
    for (int ni = 0; ni < 4; ni++)
        fb[ni] = __ldg(bias + N_OUT + oBase + ni);

    float F0[4], U0[4], F1[4], U1[4];
#pragma unroll
    for (int ni = 0; ni < 4; ni++) {
        F0[ni] = 1.0f; U0[ni] = 0.0f; F1[ni] = 1.0f; U1[ni] = 0.0f;
    }

#pragma unroll
    for (int mi = 0; mi < 4; mi++) {
        const int r0 = rBase + mi * 16;
        const int r1 = r0 + 8;
        float4 u0v, f0v, u1v, f1v;
#pragma unroll
        for (int ni = 0; ni < 4; ni++) {
            float f0 = sigmoidf_(acc[mi][ni][1] + fb[ni]);
            float u0 = acc[mi][ni][0] * (1.0f - f0);
            float f1 = sigmoidf_(acc[mi][ni][3] + fb[ni]);
            float u1 = acc[mi][ni][2] * (1.0f - f1);
            (&u0v.x)[ni] = u0; (&f0v.x)[ni] = f0;
            (&u1v.x)[ni] = u1; (&f1v.x)[ni] = f1;
            U0[ni] = fmaf(U0[ni], f0, u0); F0[ni] *= f0;
            U1[ni] = fmaf(U1[ni], f1, u1); F1[ni] *= f1;
        }
        *reinterpret_cast<float4*>(u0_out + (size_t)r0 * N_OUT + oBase) = u0v;
        *reinterpret_cast<float4*>(f_out  + (size_t)r0 * N_OUT + oBase) = f0v;
        *reinterpret_cast<float4*>(u0_out + (size_t)r1 * N_OUT + oBase) = u1v;
        *reinterpret_cast<float4*>(f_out  + (size_t)r1 * N_OUT + oBase) = f1v;
    }

    // part[((wM*4+wN)*2+half)*32+lane][ni]
#pragma unroll
    for (int ni = 0; ni < 4; ni++) {
        int base0 = ((((warpM * 4 + warpN) * 2 + 0) * 32) + lid) * 4 + ni;
        int base1 = ((((warpM * 4 + warpN) * 2 + 1) * 32) + lid) * 4 + ni;
        part[base0] = make_float2(F0[ni], U0[ni]);
        part[base1] = make_float2(F1[ni], U1[ni]);
    }
    __syncthreads();

    // combine partials across warpM (l-order); float4 writes to g_F/g_U
    const int seg = blockIdx.y;
    {
        int iwN   = tid >> 6;          // 0..3
        int ihalf = (tid >> 5) & 1;
        int ilane = tid & 31;
        float Fv[4], Uv[4];
#pragma unroll
        for (int ni = 0; ni < 4; ni++) {
            float F = 1.0f, U = 0.0f;
#pragma unroll
            for (int w = 0; w < 2; w++) {
                float2 p = part[((((w * 4 + iwN) * 2 + ihalf) * 32) + ilane) * 4 + ni];
                U = fmaf(U, p.x, p.y);
                F *= p.x;
            }
            Fv[ni] = F; Uv[ni] = U;
        }
        int b  = (ilane >> 2) + ihalf * 8;
        int j0 = b * N_OUT + blockIdx.x * 64 + iwN * 16 + (ilane & 3) * 4;
        *reinterpret_cast<float4*>(&g_F[seg][j0]) =
            make_float4(Fv[0], Fv[1], Fv[2], Fv[3]);
        *reinterpret_cast<float4*>(&g_U[seg][j0]) =
            make_float4(Uv[0], Uv[1], Uv[2], Uv[3]);
    }
}

// ---------------------------------------------------------------------------
// Phase B: warp-parallel affine scan over 256 segments.
// 512 threads = 16 warps, one chain per warp; float4 global transfers.
// ---------------------------------------------------------------------------
__global__ __launch_bounds__(512)
void scan_phaseB(const float* __restrict__ c_init,
                 float* __restrict__ c_final) {
    __shared__ float sF[16][257];
    __shared__ float sU[16][257];

    const int tid = threadIdx.x;
    const int jBase = blockIdx.x * 16;

#pragma unroll
    for (int it = 0; it < 2; it++) {
        int idx = it * 512 + tid;          // 0..1023
        int s = idx >> 2, jb = idx & 3;    // s: segment, jb: chain-block of 4
        float4 vF = *reinterpret_cast<const float4*>(&g_F[s][jBase + jb * 4]);
        float4 vU = *reinterpret_cast<const float4*>(&g_U[s][jBase + jb * 4]);
        sF[jb * 4 + 0][s] = vF.x; sF[jb * 4 + 1][s] = vF.y;
        sF[jb * 4 + 2][s] = vF.z; sF[jb * 4 + 3][s] = vF.w;
        sU[jb * 4 + 0][s] = vU.x; sU[jb * 4 + 1][s] = vU.y;
        sU[jb * 4 + 2][s] = vU.z; sU[jb * 4 + 3][s] = vU.w;
    }
    __syncthreads();

    const int w = tid >> 5;        // 0..15: chain within block
    const int lane = tid & 31;
    const int j = jBase + w;

    float Pf[8], Pu[8];
#pragma unroll
    for (int k = 0; k < 8; k++) {
        float Fk = sF[w][lane * 8 + k];
        float Uk = sU[w][lane * 8 + k];
        if (k == 0) { Pf[0] = Fk; Pu[0] = Uk; }
        else        { Pf[k] = Pf[k - 1] * Fk; Pu[k] = fmaf(Pu[k - 1], Fk, Uk); }
    }

    float tf = Pf[7], tu = Pu[7];
#pragma unroll
    for (int d = 1; d < 32; d <<= 1) {
        float of = __shfl_up_sync(0xffffffffu, tf, d);
        float ou = __shfl_up_sync(0xffffffffu, tu, d);
        if (lane >= d) {
            tu = fmaf(ou, tf, tu);
            tf = of * tf;
        }
    }
    float ef = __shfl_up_sync(0xffffffffu, tf, 1);
    float eu = __shfl_up_sync(0xffffffffu, tu, 1);
    if (lane == 0) { ef = 1.0f; eu = 0.0f; }

    const float c0 = c_init[j];
    sF[w][lane * 8] = fmaf(c0, ef, eu);
#pragma unroll
    for (int k = 1; k < 8; k++)
        sF[w][lane * 8 + k] = fmaf(c0, ef * Pf[k - 1], fmaf(eu, Pf[k - 1], Pu[k - 1]));

    if (lane == 31)
        c_final[j] = fmaf(c0, tf, tu);

    __syncthreads();
#pragma unroll
    for (int it = 0; it < 2; it++) {
        int idx = it * 512 + tid;
        int s = idx >> 2, jb = idx & 3;
        float4 vc = make_float4(sF[jb * 4 + 0][s], sF[jb * 4 + 1][s],
                                sF[jb * 4 + 2][s], sF[jb * 4 + 3][s]);
        *reinterpret_cast<float4*>(&g_Cin[s][jBase + jb * 4]) = vc;
    }
}

// ---------------------------------------------------------------------------
// Phase C: replay. 256 segments x 8 steps.
// ---------------------------------------------------------------------------
__global__ __launch_bounds__(256)
void scan_phaseC(float* __restrict__ cs,
                 const float* __restrict__ f) {
    const int j = blockIdx.x * 256 + threadIdx.x;
    const int s = blockIdx.y;
    size_t idx = (size_t)s * SEG_LEN * NCH + j;
    float c = g_Cin[s][j];
#pragma unroll
    for (int t = 0; t < SEG_LEN; t++) {
        float ft = f[idx];
        float ut = cs[idx];
        c = fmaf(c, ft, ut);
        cs[idx] = c;
        idx += NCH;
    }
}

// ---------------------------------------------------------------------------
extern "C" void kernel_launch(void* const* d_in, const int* in_sizes, int n_in,
                              void* d_out, int out_size)
{
    const float* input  = (const float*)d_in[0];
    const float* c_init = (const float*)d_in[1];
    const float* weight = (const float*)d_in[2];
    const float* bias   = (const float*)d_in[3];

    float* out    = (float*)d_out;
    float* cs     = out + CS_OFF;
    float* cfin   = out + CFINAL_OFF;
    float* forget = out + FORGET_OFF;

    cudaFuncSetAttribute(gemm_mma_kernel,
                         cudaFuncAttributeMaxDynamicSharedMemorySize, SMEM_TOTAL);

    convert_a_kernel<<<(M_ROWS * K_DIM) / (256 * 8), 256>>>(input);
    convert_b_kernel<<<dim3(N_COLS / 32, K_DIM / 32), 256>>>(weight);

    dim3 grid(N_COLS / 128, M_ROWS / 128);   // (16, 256) — blockIdx.y = segment
    gemm_mma_kernel<<<grid, 256, SMEM_TOTAL>>>(bias, cs, forget);

    scan_phaseB<<<NCH / 16, 512>>>(c_init, cfin);   // 1024 blocks, 16 chains each
    dim3 cgrid(NCH / 256, SEGS);
    scan_phaseC<<<cgrid, 256>>>(cs, forget);
}

// round 16
// speedup vs baseline: 1.0704x; 1.0156x over previous
#include <cuda_runtime.h>
#include <cuda_fp16.h>
#include <stdint.h>

#define L_SEQ   2048
#define BATCH   16
#define N_IN    1024
#define N_OUT   1024
#define M_ROWS  (L_SEQ * BATCH)      // 32768
#define N_COLS  (2 * N_OUT)          // 2048
#define K_DIM   1024
#define NCH     (BATCH * N_OUT)      // 16384 chains

#define CS_OFF      0
#define CFINAL_OFF  (M_ROWS * N_OUT)
#define FORGET_OFF  (M_ROWS * N_OUT + BATCH * N_OUT)

// fp16 operands. A: [32768,1024] k-contig. B = fp16(W^T): [2048,1024],
// rows gate-permuted within each 32-row slice (4x4 transpose of gate index).
__device__ __half g_Ah[(size_t)M_ROWS * K_DIM];
__device__ __half g_Bh[(size_t)N_COLS * K_DIM];

// scan scratch. One segment = one GEMM M-tile = 8 l-steps.
#define SEGS 256
#define SEG_LEN (L_SEQ / SEGS)       // 8
__device__ float g_F  [SEGS][NCH];
__device__ float g_U  [SEGS][NCH];
__device__ float g_Cin[SEGS][NCH];

// ---------------------------------------------------------------------------
__device__ __forceinline__ uint32_t s2u(const void* p) {
    uint32_t r;
    asm("{ .reg .u64 t; cvta.to.shared.u64 t, %1; cvt.u32.u64 %0, t; }"
        : "=r"(r) : "l"(p));
    return r;
}
__device__ __forceinline__ void cp16(uint32_t saddr, const void* gptr) {
    uint64_t g = (uint64_t)__cvta_generic_to_global(gptr);
    asm volatile("cp.async.cg.shared.global [%0], [%1], 16;"
                 :: "r"(saddr), "l"(g) : "memory");
}
__device__ __forceinline__ void cp_commit() {
    asm volatile("cp.async.commit_group;" ::: "memory");
}
template <int N>
__device__ __forceinline__ void cp_wait() {
    asm volatile("cp.async.wait_group %0;" :: "n"(N) : "memory");
}
__device__ __forceinline__ void ldsm4(uint32_t* r, uint32_t addr) {
    asm volatile("ldmatrix.sync.aligned.m8n8.x4.shared.b16 {%0,%1,%2,%3}, [%4];"
                 : "=r"(r[0]), "=r"(r[1]), "=r"(r[2]), "=r"(r[3]) : "r"(addr));
}
__device__ __forceinline__ void mma16816(float* d, const uint32_t* a, const uint32_t* b) {
    asm volatile(
        "mma.sync.aligned.m16n8k16.row.col.f32.f16.f16.f32 "
        "{%0,%1,%2,%3}, {%4,%5,%6,%7}, {%8,%9}, {%0,%1,%2,%3};"
        : "+f"(d[0]), "+f"(d[1]), "+f"(d[2]), "+f"(d[3])
        : "r"(a[0]), "r"(a[1]), "r"(a[2]), "r"(a[3]), "r"(b[0]), "r"(b[1]));
}
__device__ __forceinline__ uint32_t swz(uint32_t off) {
    return off ^ ((off >> 3) & 0x70);
}
__device__ __forceinline__ float sigmoidf_(float x) {
    return 1.0f / (1.0f + __expf(-x));
}

// ---------------------------------------------------------------------------
// Operand prep
// ---------------------------------------------------------------------------
__global__ __launch_bounds__(256)
void convert_a_kernel(const float* __restrict__ A) {
    size_t i = ((size_t)blockIdx.x * 256 + threadIdx.x) * 8;
    float4 v0 = *reinterpret_cast<const float4*>(A + i);
    float4 v1 = *reinterpret_cast<const float4*>(A + i + 4);
    __half2 h0 = __floats2half2_rn(v0.x, v0.y);
    __half2 h1 = __floats2half2_rn(v0.z, v0.w);
    __half2 h2 = __floats2half2_rn(v1.x, v1.y);
    __half2 h3 = __floats2half2_rn(v1.z, v1.w);
    uint4 pk;
    pk.x = *reinterpret_cast<uint32_t*>(&h0);
    pk.y = *reinterpret_cast<uint32_t*>(&h1);
    pk.z = *reinterpret_cast<uint32_t*>(&h2);
    pk.w = *reinterpret_cast<uint32_t*>(&h3);
    *reinterpret_cast<uint4*>(g_Ah + i) = pk;
}

// Transpose W[k][n] -> B[n_phys][k] with gate permutation: within each
// 32-row (16-gate) slice, physical gate gp = (g&3)*4 + (g>>2).
__global__ __launch_bounds__(256)
void convert_b_kernel(const float* __restrict__ W) {
    __shared__ float t[32][33];
    int n0 = blockIdx.x * 32;
    int k0 = blockIdx.y * 32;
    int tx = threadIdx.x & 31;
    int ty = threadIdx.x >> 5;
#pragma unroll
    for (int i = 0; i < 4; i++)
        t[ty + i * 8][tx] = W[(size_t)(k0 + ty + i * 8) * N_COLS + n0 + tx];
    __syncthreads();
#pragma unroll
    for (int i = 0; i < 4; i++) {
        int n = ty + i * 8;                 // 0..31 within slice
        int g   = n >> 1, par = n & 1;
        int gp  = ((g & 3) << 2) | (g >> 2);
        int n_phys = n0 + (gp << 1) + par;
        g_Bh[(size_t)n_phys * K_DIM + k0 + tx] = __float2half_rn(t[tx][n]);
    }
}

// ---------------------------------------------------------------------------
// GEMM: BM=128, BN=128, BK=64, 128 threads = 4 warps (2M x 2N),
// warp tile 64x64. 3-stage cp.async pipeline, 2 CTAs per SM.
// Bigger warp tile cuts smem-crossbar traffic 25% (A re-read x4 -> x2).
// Gate-permuted B -> float4 stores. Fused phaseA summaries, SEG_LEN=8.
// ---------------------------------------------------------------------------
#define BK 64
#define OFF_A 0
#define OFF_B 16384
#define STAGE_BYTES 32768
#define NSTAGE 3
#define SMEM_TOTAL (NSTAGE * STAGE_BYTES)   // 98304
#define NCHUNK (K_DIM / BK)                 // 16
#define NTHREADS 128

__device__ __forceinline__ void load_stage(uint32_t sbase, int tid,
                                           int rowBase, int colBase, int k0) {
    const char* ah = reinterpret_cast<const char*>(g_Ah);
    const char* bh = reinterpret_cast<const char*>(g_Bh);
#pragma unroll
    for (int i = 0; i < 8; i++) {               // A: 128 rows x 8 x 16B
        int idx = i * NTHREADS + tid;
        int row = idx >> 3, c = idx & 7;
        uint32_t so = swz((uint32_t)(row * 128 + c * 16));
        size_t go = ((size_t)(rowBase + row) * K_DIM + k0) * 2 + c * 16;
        cp16(sbase + OFF_A + so, ah + go);
    }
#pragma unroll
    for (int i = 0; i < 8; i++) {               // B: 128 rows x 8 x 16B
        int idx = i * NTHREADS + tid;
        int row = idx >> 3, c = idx & 7;
        uint32_t so = swz((uint32_t)(row * 128 + c * 16));
        size_t go = ((size_t)(colBase + row) * K_DIM + k0) * 2 + c * 16;
        cp16(sbase + OFF_B + so, bh + go);
    }
    cp_commit();
}

__global__ __launch_bounds__(NTHREADS, 2)
void gemm_mma_kernel(const float* __restrict__ bias,
                     float* __restrict__ u0_out,
                     float* __restrict__ f_out) {
    extern __shared__ __align__(128) char smem[];
    const uint32_t sb = s2u(smem);
    const int tid = threadIdx.x;
    const int lid = tid & 31;
    const int wid = tid >> 5;            // 0..3
    const int warpM = wid & 1;           // 2 x 64-row slices
    const int warpN = wid >> 1;          // 2 x 64-col slices
    const int colBase = blockIdx.x * 128;
    const int rowBase = blockIdx.y * 128;

    float acc[4][8][4];
#pragma unroll
    for (int mi = 0; mi < 4; mi++)
#pragma unroll
        for (int ni = 0; ni < 8; ni++)
#pragma unroll
            for (int e = 0; e < 4; e++)
                acc[mi][ni][e] = 0.0f;

    // prologue: fill 3 stages (chunks 0..2)
#pragma unroll
    for (int s = 0; s < NSTAGE; s++)
        load_stage(sb + s * STAGE_BYTES, tid, rowBase, colBase, s * BK);

    // Precomputed ldsm bases (kIn2 folded into swizzle).
    const int aRowIn = warpM * 64 + (lid & 15);
    const int aKIn2  = ((lid >> 4) * 8) * 2;
    const int bRowIn = warpN * 64 + (lid & 7) + ((lid >> 4) & 1) * 8;
    const int bKIn2  = (((lid >> 3) & 1) * 8) * 2;
    uint32_t aBase[4], bBase[4];
#pragma unroll
    for (int mi = 0; mi < 4; mi++)
        aBase[mi] = swz((uint32_t)((aRowIn + mi * 16) * 128 + aKIn2)) + OFF_A;
#pragma unroll
    for (int nt = 0; nt < 4; nt++)
        bBase[nt] = swz((uint32_t)((bRowIn + nt * 16) * 128 + bKIn2)) + OFF_B;

    for (int c = 0; c < NCHUNK; c++) {
        if (c == 0)       cp_wait<2>();
        else if (c < 15)  cp_wait<1>();
        else              cp_wait<0>();
        __syncthreads();

        if (c >= 1 && c + 2 < NCHUNK)
            load_stage(sb + ((c + 2) % 3) * STAGE_BYTES, tid,
                       rowBase, colBase, (c + 2) * BK);

        const uint32_t sbase = sb + (c % 3) * STAGE_BYTES;
        uint32_t aP[4], bP[4];
#pragma unroll
        for (int mi = 0; mi < 4; mi++) aP[mi] = sbase + aBase[mi];
#pragma unroll
        for (int nt = 0; nt < 4; nt++) bP[nt] = sbase + bBase[nt];

#pragma unroll
        for (int ks = 0; ks < 4; ks++) {
            const uint32_t kx = (uint32_t)(ks * 32);
            uint32_t ah[4][4];
#pragma unroll
            for (int mi = 0; mi < 4; mi++)
                ldsm4(ah[mi], aP[mi] ^ kx);
            uint32_t bh[8][2];
#pragma unroll
            for (int nt = 0; nt < 4; nt++) {
                uint32_t r[4];
                ldsm4(r, bP[nt] ^ kx);
                bh[nt * 2][0] = r[0]; bh[nt * 2][1] = r[1];
                bh[nt * 2 + 1][0] = r[2]; bh[nt * 2 + 1][1] = r[3];
            }
#pragma unroll
            for (int mi = 0; mi < 4; mi++)
#pragma unroll
                for (int ni = 0; ni < 8; ni++)
                    mma16816(acc[mi][ni], ah[mi], bh[ni]);
        }
    }
    __syncthreads();   // safe to reuse smem for scan partials

    // ------------- epilogue: gates (float4 stores) + fused summary -------------
    // Warp covers 64 cols = 2 gate-slices of 16 gates. Within slice s2 (=ni>>2),
    // lane c=(lid&3) holds LOGICAL gates sliceBase + 4c + (ni&3).
    float2* part = reinterpret_cast<float2*>(smem);
    // part[(((wM*2+wN)*2+half)*32+lane)*8 + slice*4 + niIn] -> 16 KB

    const int rBase = rowBase + warpM * 64 + (lid >> 2);
    const int gateWarp = (colBase >> 1) + warpN * 32;   // first gate of warp
    const int c4 = (lid & 3) * 4;

    float fb[8];
#pragma unroll
    for (int ni = 0; ni < 8; ni++)
        fb[ni] = __ldg(bias + N_OUT + gateWarp + (ni >> 2) * 16 + c4 + (ni & 3));

    float F0[8], U0[8], F1[8], U1[8];
#pragma unroll
    for (int ni = 0; ni < 8; ni++) {
        F0[ni] = 1.0f; U0[ni] = 0.0f; F1[ni] = 1.0f; U1[ni] = 0.0f;
    }

#pragma unroll
    for (int mi = 0; mi < 4; mi++) {
        const int r0 = rBase + mi * 16;
        const int r1 = r0 + 8;
#pragma unroll
        for (int s2 = 0; s2 < 2; s2++) {
            const int oB = gateWarp + s2 * 16 + c4;
            float4 u0v, f0v, u1v, f1v;
#pragma unroll
            for (int q = 0; q < 4; q++) {
                int ni = s2 * 4 + q;
                float f0 = sigmoidf_(acc[mi][ni][1] + fb[ni]);
                float u0 = acc[mi][ni][0] * (1.0f - f0);
                float f1 = sigmoidf_(acc[mi][ni][3] + fb[ni]);
                float u1 = acc[mi][ni][2] * (1.0f - f1);
                (&u0v.x)[q] = u0; (&f0v.x)[q] = f0;
                (&u1v.x)[q] = u1; (&f1v.x)[q] = f1;
                U0[ni] = fmaf(U0[ni], f0, u0); F0[ni] *= f0;
                U1[ni] = fmaf(U1[ni], f1, u1); F1[ni] *= f1;
            }
            *reinterpret_cast<float4*>(u0_out + (size_t)r0 * N_OUT + oB) = u0v;
            *reinterpret_cast<float4*>(f_out  + (size_t)r0 * N_OUT + oB) = f0v;
            *reinterpret_cast<float4*>(u0_out + (size_t)r1 * N_OUT + oB) = u1v;
            *reinterpret_cast<float4*>(f_out  + (size_t)r1 * N_OUT + oB) = f1v;
        }
    }

#pragma unroll
    for (int ni = 0; ni < 8; ni++) {
        int g = (warpM * 2 + warpN) * 2;
        part[((g + 0) * 32 + lid) * 8 + ni] = make_float2(F0[ni], U0[ni]);
        part[((g + 1) * 32 + lid) * 8 + ni] = make_float2(F1[ni], U1[ni]);
    }
    __syncthreads();

    // combine partials across warpM (l-order); float4 writes to g_F/g_U
    const int seg = blockIdx.y;
#pragma unroll
    for (int it = 0; it < 2; it++) {
        int item = it * NTHREADS + tid;       // [wN(1b)|half(1b)|lane(5b)|slice(1b)]
        int iwN   = item >> 7;
        int ihalf = (item >> 6) & 1;
        int ilane = (item >> 1) & 31;
        int isl   = item & 1;
        float Fv[4], Uv[4];
#pragma unroll
        for (int q = 0; q < 4; q++) {
            float F = 1.0f, U = 0.0f;
#pragma unroll
            for (int w = 0; w < 2; w++) {
                float2 p = part[((((w * 2 + iwN) * 2 + ihalf) * 32) + ilane) * 8
                                + isl * 4 + q];
                U = fmaf(U, p.x, p.y);
                F *= p.x;
            }
            Fv[q] = F; Uv[q] = U;
        }
        int b  = (ilane >> 2) + ihalf * 8;
        int j0 = b * N_OUT + blockIdx.x * 64 + iwN * 32 + isl * 16 + (ilane & 3) * 4;
        *reinterpret_cast<float4*>(&g_F[seg][j0]) =
            make_float4(Fv[0], Fv[1], Fv[2], Fv[3]);
        *reinterpret_cast<float4*>(&g_U[seg][j0]) =
            make_float4(Uv[0], Uv[1], Uv[2], Uv[3]);
    }
}

// ---------------------------------------------------------------------------
// Phase B: warp-parallel affine scan over 256 segments.
// 512 threads = 16 warps, one chain per warp; float4 global transfers.
// ---------------------------------------------------------------------------
__global__ __launch_bounds__(512)
void scan_phaseB(const float* __restrict__ c_init,
                 float* __restrict__ c_final) {
    __shared__ float sF[16][257];
    __shared__ float sU[16][257];

    const int tid = threadIdx.x;
    const int jBase = blockIdx.x * 16;

#pragma unroll
    for (int it = 0; it < 2; it++) {
        int idx = it * 512 + tid;
        int s = idx >> 2, jb = idx & 3;
        float4 vF = *reinterpret_cast<const float4*>(&g_F[s][jBase + jb * 4]);
        float4 vU = *reinterpret_cast<const float4*>(&g_U[s][jBase + jb * 4]);
        sF[jb * 4 + 0][s] = vF.x; sF[jb * 4 + 1][s] = vF.y;
        sF[jb * 4 + 2][s] = vF.z; sF[jb * 4 + 3][s] = vF.w;
        sU[jb * 4 + 0][s] = vU.x; sU[jb * 4 + 1][s] = vU.y;
        sU[jb * 4 + 2][s] = vU.z; sU[jb * 4 + 3][s] = vU.w;
    }
    __syncthreads();

    const int w = tid >> 5;
    const int lane = tid & 31;
    const int j = jBase + w;

    float Pf[8], Pu[8];
#pragma unroll
    for (int k = 0; k < 8; k++) {
        float Fk = sF[w][lane * 8 + k];
        float Uk = sU[w][lane * 8 + k];
        if (k == 0) { Pf[0] = Fk; Pu[0] = Uk; }
        else        { Pf[k] = Pf[k - 1] * Fk; Pu[k] = fmaf(Pu[k - 1], Fk, Uk); }
    }

    float tf = Pf[7], tu = Pu[7];
#pragma unroll
    for (int d = 1; d < 32; d <<= 1) {
        float of = __shfl_up_sync(0xffffffffu, tf, d);
        float ou = __shfl_up_sync(0xffffffffu, tu, d);
        if (lane >= d) {
            tu = fmaf(ou, tf, tu);
            tf = of * tf;
        }
    }
    float ef = __shfl_up_sync(0xffffffffu, tf, 1);
    float eu = __shfl_up_sync(0xffffffffu, tu, 1);
    if (lane == 0) { ef = 1.0f; eu = 0.0f; }

    const float c0 = c_init[j];
    sF[w][lane * 8] = fmaf(c0, ef, eu);
#pragma unroll
    for (int k = 1; k < 8; k++)
        sF[w][lane * 8 + k] = fmaf(c0, ef * Pf[k - 1], fmaf(eu, Pf[k - 1], Pu[k - 1]));

    if (lane == 31)
        c_final[j] = fmaf(c0, tf, tu);

    __syncthreads();
#pragma unroll
    for (int it = 0; it < 2; it++) {
        int idx = it * 512 + tid;
        int s = idx >> 2, jb = idx & 3;
        float4 vc = make_float4(sF[jb * 4 + 0][s], sF[jb * 4 + 1][s],
                                sF[jb * 4 + 2][s], sF[jb * 4 + 3][s]);
        *reinterpret_cast<float4*>(&g_Cin[s][jBase + jb * 4]) = vc;
    }
}

// ---------------------------------------------------------------------------
// Phase C: replay. 256 segments x 8 steps.
// ---------------------------------------------------------------------------
__global__ __launch_bounds__(256)
void scan_phaseC(float* __restrict__ cs,
                 const float* __restrict__ f) {
    const int j = blockIdx.x * 256 + threadIdx.x;
    const int s = blockIdx.y;
    size_t idx = (size_t)s * SEG_LEN * NCH + j;
    float c = g_Cin[s][j];
#pragma unroll
    for (int t = 0; t < SEG_LEN; t++) {
        float ft = f[idx];
        float ut = cs[idx];
        c = fmaf(c, ft, ut);
        cs[idx] = c;
        idx += NCH;
    }
}

// ---------------------------------------------------------------------------
extern "C" void kernel_launch(void* const* d_in, const int* in_sizes, int n_in,
                              void* d_out, int out_size)
{
    const float* input  = (const float*)d_in[0];
    const float* c_init = (const float*)d_in[1];
    const float* weight = (const float*)d_in[2];
    const float* bias   = (const float*)d_in[3];

    float* out    = (float*)d_out;
    float* cs     = out + CS_OFF;
    float* cfin   = out + CFINAL_OFF;
    float* forget = out + FORGET_OFF;

    cudaFuncSetAttribute(gemm_mma_kernel,
                         cudaFuncAttributeMaxDynamicSharedMemorySize, SMEM_TOTAL);

    convert_a_kernel<<<(M_ROWS * K_DIM) / (256 * 8), 256>>>(input);
    convert_b_kernel<<<dim3(N_COLS / 32, K_DIM / 32), 256>>>(weight);

    dim3 grid(N_COLS / 128, M_ROWS / 128);   // (16, 256) — blockIdx.y = segment
    gemm_mma_kernel<<<grid, NTHREADS, SMEM_TOTAL>>>(bias, cs, forget);

    scan_phaseB<<<NCH / 16, 512>>>(c_init, cfin);   // 1024 blocks, 16 chains each
    dim3 cgrid(NCH / 256, SEGS);
    scan_phaseC<<<cgrid, 256>>>(cs, forget);
}

// round 17
// speedup vs baseline: 1.0947x; 1.0227x over previous
#include <cuda_runtime.h>
#include <cuda_fp16.h>
#include <stdint.h>

#define L_SEQ   2048
#define BATCH   16
#define N_IN    1024
#define N_OUT   1024
#define M_ROWS  (L_SEQ * BATCH)      // 32768
#define N_COLS  (2 * N_OUT)          // 2048
#define K_DIM   1024
#define NCH     (BATCH * N_OUT)      // 16384 chains

#define CS_OFF      0
#define CFINAL_OFF  (M_ROWS * N_OUT)
#define FORGET_OFF  (M_ROWS * N_OUT + BATCH * N_OUT)

// fp16 operands. A: [32768,1024] k-contig. B = fp16(W^T): [2048,1024],
// rows gate-permuted within each 32-row slice (4x4 transpose of gate index).
__device__ __half g_Ah[(size_t)M_ROWS * K_DIM];
__device__ __half g_Bh[(size_t)N_COLS * K_DIM];

// scan scratch. One segment = one GEMM M-tile = 8 l-steps.
#define SEGS 256
#define SEG_LEN (L_SEQ / SEGS)       // 8
__device__ float g_F  [SEGS][NCH];
__device__ float g_U  [SEGS][NCH];
__device__ float g_Cin[SEGS][NCH];

// ---------------------------------------------------------------------------
__device__ __forceinline__ uint32_t s2u(const void* p) {
    uint32_t r;
    asm("{ .reg .u64 t; cvta.to.shared.u64 t, %1; cvt.u32.u64 %0, t; }"
        : "=r"(r) : "l"(p));
    return r;
}
__device__ __forceinline__ void cp16(uint32_t saddr, const void* gptr) {
    uint64_t g = (uint64_t)__cvta_generic_to_global(gptr);
    asm volatile("cp.async.cg.shared.global [%0], [%1], 16;"
                 :: "r"(saddr), "l"(g) : "memory");
}
__device__ __forceinline__ void cp_commit() {
    asm volatile("cp.async.commit_group;" ::: "memory");
}
template <int N>
__device__ __forceinline__ void cp_wait() {
    asm volatile("cp.async.wait_group %0;" :: "n"(N) : "memory");
}
__device__ __forceinline__ void ldsm4(uint32_t* r, uint32_t addr) {
    asm volatile("ldmatrix.sync.aligned.m8n8.x4.shared.b16 {%0,%1,%2,%3}, [%4];"
                 : "=r"(r[0]), "=r"(r[1]), "=r"(r[2]), "=r"(r[3]) : "r"(addr));
}
__device__ __forceinline__ void mma16816(float* d, const uint32_t* a, const uint32_t* b) {
    asm volatile(
        "mma.sync.aligned.m16n8k16.row.col.f32.f16.f16.f32 "
        "{%0,%1,%2,%3}, {%4,%5,%6,%7}, {%8,%9}, {%0,%1,%2,%3};"
        : "+f"(d[0]), "+f"(d[1]), "+f"(d[2]), "+f"(d[3])
        : "r"(a[0]), "r"(a[1]), "r"(a[2]), "r"(a[3]), "r"(b[0]), "r"(b[1]));
}
__device__ __forceinline__ uint32_t swz(uint32_t off) {
    return off ^ ((off >> 3) & 0x70);
}
__device__ __forceinline__ float sigmoidf_(float x) {
    return 1.0f / (1.0f + __expf(-x));
}

// ---------------------------------------------------------------------------
// Merged operand prep: blocks [0, NA) convert A, blocks [NA, NA+NB) do W^T.
// ---------------------------------------------------------------------------
#define NA_BLOCKS ((M_ROWS * K_DIM) / (256 * 8))     // 16384
#define NB_BLOCKS ((N_COLS / 32) * (K_DIM / 32))     // 2048

__global__ __launch_bounds__(256)
void convert_ab_kernel(const float* __restrict__ A,
                       const float* __restrict__ W) {
    __shared__ float t[32][33];
    const int bid = blockIdx.x;
    if (bid < NA_BLOCKS) {
        size_t i = ((size_t)bid * 256 + threadIdx.x) * 8;
        float4 v0 = *reinterpret_cast<const float4*>(A + i);
        float4 v1 = *reinterpret_cast<const float4*>(A + i + 4);
        __half2 h0 = __floats2half2_rn(v0.x, v0.y);
        __half2 h1 = __floats2half2_rn(v0.z, v0.w);
        __half2 h2 = __floats2half2_rn(v1.x, v1.y);
        __half2 h3 = __floats2half2_rn(v1.z, v1.w);
        uint4 pk;
        pk.x = *reinterpret_cast<uint32_t*>(&h0);
        pk.y = *reinterpret_cast<uint32_t*>(&h1);
        pk.z = *reinterpret_cast<uint32_t*>(&h2);
        pk.w = *reinterpret_cast<uint32_t*>(&h3);
        *reinterpret_cast<uint4*>(g_Ah + i) = pk;
    } else {
        const int b2 = bid - NA_BLOCKS;
        const int n0 = (b2 & 63) * 32;          // 64 n-tiles
        const int k0 = (b2 >> 6) * 32;          // 32 k-tiles
        const int tx = threadIdx.x & 31;
        const int ty = threadIdx.x >> 5;
#pragma unroll
        for (int i = 0; i < 4; i++)
            t[ty + i * 8][tx] = W[(size_t)(k0 + ty + i * 8) * N_COLS + n0 + tx];
        __syncthreads();
#pragma unroll
        for (int i = 0; i < 4; i++) {
            int n = ty + i * 8;                 // 0..31 within slice
            int g   = n >> 1, par = n & 1;
            int gp  = ((g & 3) << 2) | (g >> 2);
            int n_phys = n0 + (gp << 1) + par;
            g_Bh[(size_t)n_phys * K_DIM + k0 + tx] = __float2half_rn(t[tx][n]);
        }
    }
}

// ---------------------------------------------------------------------------
// GEMM: BM=128, BN=128, BK=64, 128 threads = 4 warps (2M x 2N),
// warp tile 64x64. 3-stage cp.async pipeline, 2 CTAs per SM.
// Gate-permuted B -> float4 stores. Fused phaseA summaries, SEG_LEN=8.
// ---------------------------------------------------------------------------
#define BK 64
#define OFF_A 0
#define OFF_B 16384
#define STAGE_BYTES 32768
#define NSTAGE 3
#define SMEM_TOTAL (NSTAGE * STAGE_BYTES)   // 98304
#define NCHUNK (K_DIM / BK)                 // 16
#define NTHREADS 128

__device__ __forceinline__ void load_stage(uint32_t sbase, int tid,
                                           int rowBase, int colBase, int k0) {
    const char* ah = reinterpret_cast<const char*>(g_Ah);
    const char* bh = reinterpret_cast<const char*>(g_Bh);
#pragma unroll
    for (int i = 0; i < 8; i++) {               // A: 128 rows x 8 x 16B
        int idx = i * NTHREADS + tid;
        int row = idx >> 3, c = idx & 7;
        uint32_t so = swz((uint32_t)(row * 128 + c * 16));
        size_t go = ((size_t)(rowBase + row) * K_DIM + k0) * 2 + c * 16;
        cp16(sbase + OFF_A + so, ah + go);
    }
#pragma unroll
    for (int i = 0; i < 8; i++) {               // B: 128 rows x 8 x 16B
        int idx = i * NTHREADS + tid;
        int row = idx >> 3, c = idx & 7;
        uint32_t so = swz((uint32_t)(row * 128 + c * 16));
        size_t go = ((size_t)(colBase + row) * K_DIM + k0) * 2 + c * 16;
        cp16(sbase + OFF_B + so, bh + go);
    }
    cp_commit();
}

__global__ __launch_bounds__(NTHREADS, 2)
void gemm_mma_kernel(const float* __restrict__ bias,
                     float* __restrict__ u0_out,
                     float* __restrict__ f_out) {
    extern __shared__ __align__(128) char smem[];
    const uint32_t sb = s2u(smem);
    const int tid = threadIdx.x;
    const int lid = tid & 31;
    const int wid = tid >> 5;            // 0..3
    const int warpM = wid & 1;           // 2 x 64-row slices
    const int warpN = wid >> 1;          // 2 x 64-col slices
    const int colBase = blockIdx.x * 128;
    const int rowBase = blockIdx.y * 128;

    float acc[4][8][4];
#pragma unroll
    for (int mi = 0; mi < 4; mi++)
#pragma unroll
        for (int ni = 0; ni < 8; ni++)
#pragma unroll
            for (int e = 0; e < 4; e++)
                acc[mi][ni][e] = 0.0f;

#pragma unroll
    for (int s = 0; s < NSTAGE; s++)
        load_stage(sb + s * STAGE_BYTES, tid, rowBase, colBase, s * BK);

    const int aRowIn = warpM * 64 + (lid & 15);
    const int aKIn2  = ((lid >> 4) * 8) * 2;
    const int bRowIn = warpN * 64 + (lid & 7) + ((lid >> 4) & 1) * 8;
    const int bKIn2  = (((lid >> 3) & 1) * 8) * 2;
    uint32_t aBase[4], bBase[4];
#pragma unroll
    for (int mi = 0; mi < 4; mi++)
        aBase[mi] = swz((uint32_t)((aRowIn + mi * 16) * 128 + aKIn2)) + OFF_A;
#pragma unroll
    for (int nt = 0; nt < 4; nt++)
        bBase[nt] = swz((uint32_t)((bRowIn + nt * 16) * 128 + bKIn2)) + OFF_B;

    for (int c = 0; c < NCHUNK; c++) {
        if (c == 0)       cp_wait<2>();
        else if (c < 15)  cp_wait<1>();
        else              cp_wait<0>();
        __syncthreads();

        if (c >= 1 && c + 2 < NCHUNK)
            load_stage(sb + ((c + 2) % 3) * STAGE_BYTES, tid,
                       rowBase, colBase, (c + 2) * BK);

        const uint32_t sbase = sb + (c % 3) * STAGE_BYTES;
        uint32_t aP[4], bP[4];
#pragma unroll
        for (int mi = 0; mi < 4; mi++) aP[mi] = sbase + aBase[mi];
#pragma unroll
        for (int nt = 0; nt < 4; nt++) bP[nt] = sbase + bBase[nt];

#pragma unroll
        for (int ks = 0; ks < 4; ks++) {
            const uint32_t kx = (uint32_t)(ks * 32);
            uint32_t ah[4][4];
#pragma unroll
            for (int mi = 0; mi < 4; mi++)
                ldsm4(ah[mi], aP[mi] ^ kx);
            uint32_t bh[8][2];
#pragma unroll
            for (int nt = 0; nt < 4; nt++) {
                uint32_t r[4];
                ldsm4(r, bP[nt] ^ kx);
                bh[nt * 2][0] = r[0]; bh[nt * 2][1] = r[1];
                bh[nt * 2 + 1][0] = r[2]; bh[nt * 2 + 1][1] = r[3];
            }
#pragma unroll
            for (int mi = 0; mi < 4; mi++)
#pragma unroll
                for (int ni = 0; ni < 8; ni++)
                    mma16816(acc[mi][ni], ah[mi], bh[ni]);
        }
    }
    __syncthreads();   // safe to reuse smem for scan partials

    // ------------- epilogue: gates (float4 stores) + fused summary -------------
    float2* part = reinterpret_cast<float2*>(smem);

    const int rBase = rowBase + warpM * 64 + (lid >> 2);
    const int gateWarp = (colBase >> 1) + warpN * 32;
    const int c4 = (lid & 3) * 4;

    float fb[8];
#pragma unroll
    for (int ni = 0; ni < 8; ni++)
        fb[ni] = __ldg(bias + N_OUT + gateWarp + (ni >> 2) * 16 + c4 + (ni & 3));

    float F0[8], U0[8], F1[8], U1[8];
#pragma unroll
    for (int ni = 0; ni < 8; ni++) {
        F0[ni] = 1.0f; U0[ni] = 0.0f; F1[ni] = 1.0f; U1[ni] = 0.0f;
    }

#pragma unroll
    for (int mi = 0; mi < 4; mi++) {
        const int r0 = rBase + mi * 16;
        const int r1 = r0 + 8;
#pragma unroll
        for (int s2 = 0; s2 < 2; s2++) {
            const int oB = gateWarp + s2 * 16 + c4;
            float4 u0v, f0v, u1v, f1v;
#pragma unroll
            for (int q = 0; q < 4; q++) {
                int ni = s2 * 4 + q;
                float f0 = sigmoidf_(acc[mi][ni][1] + fb[ni]);
                float u0 = acc[mi][ni][0] * (1.0f - f0);
                float f1 = sigmoidf_(acc[mi][ni][3] + fb[ni]);
                float u1 = acc[mi][ni][2] * (1.0f - f1);
                (&u0v.x)[q] = u0; (&f0v.x)[q] = f0;
                (&u1v.x)[q] = u1; (&f1v.x)[q] = f1;
                U0[ni] = fmaf(U0[ni], f0, u0); F0[ni] *= f0;
                U1[ni] = fmaf(U1[ni], f1, u1); F1[ni] *= f1;
            }
            *reinterpret_cast<float4*>(u0_out + (size_t)r0 * N_OUT + oB) = u0v;
            *reinterpret_cast<float4*>(f_out  + (size_t)r0 * N_OUT + oB) = f0v;
            *reinterpret_cast<float4*>(u0_out + (size_t)r1 * N_OUT + oB) = u1v;
            *reinterpret_cast<float4*>(f_out  + (size_t)r1 * N_OUT + oB) = f1v;
        }
    }

#pragma unroll
    for (int ni = 0; ni < 8; ni++) {
        int g = (warpM * 2 + warpN) * 2;
        part[((g + 0) * 32 + lid) * 8 + ni] = make_float2(F0[ni], U0[ni]);
        part[((g + 1) * 32 + lid) * 8 + ni] = make_float2(F1[ni], U1[ni]);
    }
    __syncthreads();

    const int seg = blockIdx.y;
#pragma unroll
    for (int it = 0; it < 2; it++) {
        int item = it * NTHREADS + tid;
        int iwN   = item >> 7;
        int ihalf = (item >> 6) & 1;
        int ilane = (item >> 1) & 31;
        int isl   = item & 1;
        float Fv[4], Uv[4];
#pragma unroll
        for (int q = 0; q < 4; q++) {
            float F = 1.0f, U = 0.0f;
#pragma unroll
            for (int w = 0; w < 2; w++) {
                float2 p = part[((((w * 2 + iwN) * 2 + ihalf) * 32) + ilane) * 8
                                + isl * 4 + q];
                U = fmaf(U, p.x, p.y);
                F *= p.x;
            }
            Fv[q] = F; Uv[q] = U;
        }
        int b  = (ilane >> 2) + ihalf * 8;
        int j0 = b * N_OUT + blockIdx.x * 64 + iwN * 32 + isl * 16 + (ilane & 3) * 4;
        *reinterpret_cast<float4*>(&g_F[seg][j0]) =
            make_float4(Fv[0], Fv[1], Fv[2], Fv[3]);
        *reinterpret_cast<float4*>(&g_U[seg][j0]) =
            make_float4(Uv[0], Uv[1], Uv[2], Uv[3]);
    }
}

// ---------------------------------------------------------------------------
// Phase B: warp-parallel affine scan over 256 segments.
// 512 threads = 16 warps, one chain per warp. Compute-phase smem access is
// float4 (LDS.128): 8-way bank conflicts -> 2-way. Rows padded to 264 floats.
// ---------------------------------------------------------------------------
#define PBROW 264
__global__ __launch_bounds__(512)
void scan_phaseB(const float* __restrict__ c_init,
                 float* __restrict__ c_final) {
    __shared__ float sF[16][PBROW];
    __shared__ float sU[16][PBROW];

    const int tid = threadIdx.x;
    const int jBase = blockIdx.x * 16;

#pragma unroll
    for (int it = 0; it < 2; it++) {
        int idx = it * 512 + tid;
        int s = idx >> 2, jb = idx & 3;
        float4 vF = *reinterpret_cast<const float4*>(&g_F[s][jBase + jb * 4]);
        float4 vU = *reinterpret_cast<const float4*>(&g_U[s][jBase + jb * 4]);
        sF[jb * 4 + 0][s] = vF.x; sF[jb * 4 + 1][s] = vF.y;
        sF[jb * 4 + 2][s] = vF.z; sF[jb * 4 + 3][s] = vF.w;
        sU[jb * 4 + 0][s] = vU.x; sU[jb * 4 + 1][s] = vU.y;
        sU[jb * 4 + 2][s] = vU.z; sU[jb * 4 + 3][s] = vU.w;
    }
    __syncthreads();

    const int w = tid >> 5;
    const int lane = tid & 31;
    const int j = jBase + w;

    float4 Fa = *reinterpret_cast<const float4*>(&sF[w][lane * 8]);
    float4 Fbv = *reinterpret_cast<const float4*>(&sF[w][lane * 8 + 4]);
    float4 Ua = *reinterpret_cast<const float4*>(&sU[w][lane * 8]);
    float4 Ubv = *reinterpret_cast<const float4*>(&sU[w][lane * 8 + 4]);
    float Fk[8] = {Fa.x, Fa.y, Fa.z, Fa.w, Fbv.x, Fbv.y, Fbv.z, Fbv.w};
    float Uk[8] = {Ua.x, Ua.y, Ua.z, Ua.w, Ubv.x, Ubv.y, Ubv.z, Ubv.w};

    float Pf[8], Pu[8];
    Pf[0] = Fk[0]; Pu[0] = Uk[0];
#pragma unroll
    for (int k = 1; k < 8; k++) {
        Pf[k] = Pf[k - 1] * Fk[k];
        Pu[k] = fmaf(Pu[k - 1], Fk[k], Uk[k]);
    }

    float tf = Pf[7], tu = Pu[7];
#pragma unroll
    for (int d = 1; d < 32; d <<= 1) {
        float of = __shfl_up_sync(0xffffffffu, tf, d);
        float ou = __shfl_up_sync(0xffffffffu, tu, d);
        if (lane >= d) {
            tu = fmaf(ou, tf, tu);
            tf = of * tf;
        }
    }
    float ef = __shfl_up_sync(0xffffffffu, tf, 1);
    float eu = __shfl_up_sync(0xffffffffu, tu, 1);
    if (lane == 0) { ef = 1.0f; eu = 0.0f; }

    const float c0 = c_init[j];
    float4 cA, cB;
    cA.x = fmaf(c0, ef, eu);
    cA.y = fmaf(c0, ef * Pf[0], fmaf(eu, Pf[0], Pu[0]));
    cA.z = fmaf(c0, ef * Pf[1], fmaf(eu, Pf[1], Pu[1]));
    cA.w = fmaf(c0, ef * Pf[2], fmaf(eu, Pf[2], Pu[2]));
    cB.x = fmaf(c0, ef * Pf[3], fmaf(eu, Pf[3], Pu[3]));
    cB.y = fmaf(c0, ef * Pf[4], fmaf(eu, Pf[4], Pu[4]));
    cB.z = fmaf(c0, ef * Pf[5], fmaf(eu, Pf[5], Pu[5]));
    cB.w = fmaf(c0, ef * Pf[6], fmaf(eu, Pf[6], Pu[6]));
    *reinterpret_cast<float4*>(&sF[w][lane * 8])     = cA;
    *reinterpret_cast<float4*>(&sF[w][lane * 8 + 4]) = cB;

    if (lane == 31)
        c_final[j] = fmaf(c0, tf, tu);

    __syncthreads();
#pragma unroll
    for (int it = 0; it < 2; it++) {
        int idx = it * 512 + tid;
        int s = idx >> 2, jb = idx & 3;
        float4 vc = make_float4(sF[jb * 4 + 0][s], sF[jb * 4 + 1][s],
                                sF[jb * 4 + 2][s], sF[jb * 4 + 3][s]);
        *reinterpret_cast<float4*>(&g_Cin[s][jBase + jb * 4]) = vc;
    }
}

// ---------------------------------------------------------------------------
// Phase C: replay. 256 segments x 8 steps.
// ---------------------------------------------------------------------------
__global__ __launch_bounds__(256)
void scan_phaseC(float* __restrict__ cs,
                 const float* __restrict__ f) {
    const int j = blockIdx.x * 256 + threadIdx.x;
    const int s = blockIdx.y;
    size_t idx = (size_t)s * SEG_LEN * NCH + j;
    float c = g_Cin[s][j];
#pragma unroll
    for (int t = 0; t < SEG_LEN; t++) {
        float ft = f[idx];
        float ut = cs[idx];
        c = fmaf(c, ft, ut);
        cs[idx] = c;
        idx += NCH;
    }
}

// ---------------------------------------------------------------------------
extern "C" void kernel_launch(void* const* d_in, const int* in_sizes, int n_in,
                              void* d_out, int out_size)
{
    const float* input  = (const float*)d_in[0];
    const float* c_init = (const float*)d_in[1];
    const float* weight = (const float*)d_in[2];
    const float* bias   = (const float*)d_in[3];

    float* out    = (float*)d_out;
    float* cs     = out + CS_OFF;
    float* cfin   = out + CFINAL_OFF;
    float* forget = out + FORGET_OFF;

    cudaFuncSetAttribute(gemm_mma_kernel,
                         cudaFuncAttributeMaxDynamicSharedMemorySize, SMEM_TOTAL);

    convert_ab_kernel<<<NA_BLOCKS + NB_BLOCKS, 256>>>(input, weight);

    dim3 grid(N_COLS / 128, M_ROWS / 128);   // (16, 256) — blockIdx.y = segment
    gemm_mma_kernel<<<grid, NTHREADS, SMEM_TOTAL>>>(bias, cs, forget);

    scan_phaseB<<<NCH / 16, 512>>>(c_init, cfin);   // 1024 blocks, 16 chains each
    dim3 cgrid(NCH / 256, SEGS);
    scan_phaseC<<<cgrid, 256>>>(cs, forget);
}